// round 15
// baseline (speedup 1.0000x reference)
#include <cuda_runtime.h>
#include <cstdint>
#include <cstddef>

// ---------------------------------------------------------------------------
// Problem dims (fixed)
// ---------------------------------------------------------------------------
#define BATCH 64
#define SEQ   2048
#define IND   256
#define UNITS 256
#define M_TOTAL (BATCH * SEQ)          // 131072

typedef unsigned long long ull;

// ---------------------------------------------------------------------------
// Device-global scratch (padded by UNITS for the x prefetch of the last step)
// ---------------------------------------------------------------------------
__device__ float g_xf[(size_t)M_TOTAL * UNITS + UNITS];
__device__ float g_xs[(size_t)M_TOTAL * UNITS + UNITS];

// ---------------------------------------------------------------------------
// Packed f32x2 helpers
// ---------------------------------------------------------------------------
__device__ __forceinline__ void fma2(ull& d, ull a, ull b) {
    asm("fma.rn.f32x2 %0, %1, %2, %0;" : "+l"(d) : "l"(a), "l"(b));
}
__device__ __forceinline__ void add2(ull& d, ull a) {
    asm("add.rn.f32x2 %0, %0, %1;" : "+l"(d) : "l"(a));
}
__device__ __forceinline__ ull pack2(float x, float y) {
    ull r;
    asm("mov.b64 %0, {%1, %2};" : "=l"(r)
        : "r"(__float_as_uint(x)), "r"(__float_as_uint(y)));
    return r;
}
__device__ __forceinline__ float2 unpack2(ull v) {
    unsigned lo, hi;
    asm("mov.b64 {%0, %1}, %2;" : "=r"(lo), "=r"(hi) : "l"(v));
    return make_float2(__uint_as_float(lo), __uint_as_float(hi));
}

// ---------------------------------------------------------------------------
// Phase 1: xf = X @ W_f + b_f ; xs = X @ W_s + b_s   (unchanged)
// ---------------------------------------------------------------------------
#define BM 128
#define BN 128
#define BK 16

__global__ __launch_bounds__(256, 2)
void gemm_in(const float* __restrict__ X,
             const float* __restrict__ Wf, const float* __restrict__ bf,
             const float* __restrict__ Ws, const float* __restrict__ bs) {
    __shared__ ull   sA[BK][BM + 2];
    __shared__ float sB[BK][BN];

    const int tid = threadIdx.x;
    const int which = blockIdx.y;
    const float* W    = (which < 2) ? Wf : Ws;
    const float* bias = (which < 2) ? bf : bs;
    float*       out  = (which < 2) ? g_xf : g_xs;
    const int    n0   = (which & 1) * BN;
    const size_t m0   = (size_t)blockIdx.x * BM;

    const int tx = tid & 15;
    const int ty = tid >> 4;

    ull acc[8][4];
#pragma unroll
    for (int i = 0; i < 8; i++)
#pragma unroll
        for (int j = 0; j < 4; j++) acc[i][j] = 0ull;

    for (int k0 = 0; k0 < IND; k0 += BK) {
#pragma unroll
        for (int it = 0; it < 2; it++) {
            int s   = tid + it * 256;
            int row = s >> 2;
            int kq  = (s & 3) * 4;
            float4 v = *(const float4*)&X[(m0 + row) * IND + k0 + kq];
            sA[kq + 0][row] = pack2(v.x, v.x);
            sA[kq + 1][row] = pack2(v.y, v.y);
            sA[kq + 2][row] = pack2(v.z, v.z);
            sA[kq + 3][row] = pack2(v.w, v.w);
        }
#pragma unroll
        for (int it = 0; it < 2; it++) {
            int s  = tid + it * 256;
            int kr = s >> 5;
            int nq = (s & 31) * 4;
            *(float4*)&sB[kr][nq] =
                *(const float4*)&W[(size_t)(k0 + kr) * UNITS + n0 + nq];
        }
        __syncthreads();

#pragma unroll
        for (int k = 0; k < BK; k++) {
            ull a[8];
#pragma unroll
            for (int i = 0; i < 8; i++) a[i] = sA[k][ty * 8 + i];
            const ull* b2 = (const ull*)&sB[k][tx * 8];
            ull b[4];
#pragma unroll
            for (int j = 0; j < 4; j++) b[j] = b2[j];
#pragma unroll
            for (int i = 0; i < 8; i++)
#pragma unroll
                for (int j = 0; j < 4; j++) fma2(acc[i][j], a[i], b[j]);
        }
        __syncthreads();
    }

    float bv[8];
#pragma unroll
    for (int j = 0; j < 8; j++) bv[j] = bias[n0 + tx * 8 + j];
#pragma unroll
    for (int i = 0; i < 8; i++) {
        size_t row = m0 + ty * 8 + i;
        float2 r0 = unpack2(acc[i][0]);
        float2 r1 = unpack2(acc[i][1]);
        float2 r2 = unpack2(acc[i][2]);
        float2 r3 = unpack2(acc[i][3]);
        float4 o0 = make_float4(r0.x + bv[0], r0.y + bv[1],
                                r1.x + bv[2], r1.y + bv[3]);
        float4 o1 = make_float4(r2.x + bv[4], r2.y + bv[5],
                                r3.x + bv[6], r3.y + bv[7]);
        *(float4*)&out[row * UNITS + n0 + tx * 8]     = o0;
        *(float4*)&out[row * UNITS + n0 + tx * 8 + 4] = o1;
    }
}

// ---------------------------------------------------------------------------
// Phase 2: cluster-2 scan, interleaved local/remote k, mbarrier signaling.
// 128 CTAs. Thread = (unit uL = t>>1, kh = t&1); lane pair combines via
// shfl.bfly(1). Thread's 128-k = 64 LOCAL (no remote wait) + 64 REMOTE.
// Cross-CTA data-ready = per-lane st.relaxed + mbarrier.arrive.release on
// the PEER's mbarrier (count=128), issued BEFORE the local __syncthreads so
// the 128 arrival flights overlap; consumers try_wait.acquire.cluster before
// their remote segment. Single-buffer safety: every reader lane's reads are
// ordered before its pair-owner's arrival via the phase shfl.
// ---------------------------------------------------------------------------
#define RFLP 8                                // local RF pairs per matrix
#define RFRP 32                               // remote RF pairs per matrix
#define SW_J 12                               // local smem slots (24 pairs)
#define SW_BYTES (SW_J * 256 * 16)            // 49152 per matrix
#define VEC_BYTES 1088                        // 256 floats + 4x16B skew
#define SH_OFF   (2 * SW_BYTES)               // 98304
#define SFH_OFF  (SH_OFF + VEC_BYTES)
#define BAR_OFF  (SFH_OFF + VEC_BYTES)        // bFH at +0, bH at +16
#define SMEM_SCAN (BAR_OFF + 64)              // 100608 bytes

__device__ __forceinline__ uint32_t ctarank() {
    uint32_t r;
    asm("mov.u32 %0, %%cluster_ctarank;" : "=r"(r));
    return r;
}
__device__ __forceinline__ uint32_t smem_u32(const void* p) {
    return (uint32_t)__cvta_generic_to_shared(p);
}
__device__ __forceinline__ uint32_t mapa_addr(const void* laddr, uint32_t peer) {
    uint32_t la = smem_u32(laddr);
    uint32_t ra;
    asm("mapa.shared::cluster.u32 %0, %1, %2;" : "=r"(ra) : "r"(la), "r"(peer));
    return ra;
}
__device__ __forceinline__ void st_rlx_remote(uint32_t ra, float v) {
    asm volatile("st.relaxed.cluster.shared::cluster.b32 [%0], %1;"
                 :: "r"(ra), "r"(__float_as_uint(v)) : "memory");
}
__device__ __forceinline__ void mbar_init(const void* bar, uint32_t count) {
    asm volatile("mbarrier.init.shared.b64 [%0], %1;"
                 :: "r"(smem_u32(bar)), "r"(count) : "memory");
}
// Per-lane arrival on the PEER CTA's mbarrier; release orders prior stores.
__device__ __forceinline__ void mbar_arrive_remote(uint32_t ra) {
    asm volatile("mbarrier.arrive.release.cluster.shared::cluster.b64 _, [%0];"
                 :: "r"(ra) : "memory");
}
// Wait on LOCAL mbarrier with cluster-scope acquire (poll loop).
__device__ __forceinline__ void mbar_wait(const void* bar, uint32_t parity) {
    uint32_t addr = smem_u32(bar);
    asm volatile(
        "{\n\t"
        ".reg .pred P1;\n\t"
        "WAIT_LOOP_%=:\n\t"
        "mbarrier.try_wait.parity.acquire.cluster.shared::cta.b64 P1, [%0], %1, 0x989680;\n\t"
        "@P1 bra.uni WAIT_DONE_%=;\n\t"
        "bra.uni WAIT_LOOP_%=;\n\t"
        "WAIT_DONE_%=:\n\t"
        "}"
        :: "r"(addr), "r"(parity) : "memory");
}

__global__ __launch_bounds__(256, 1) __cluster_dims__(2, 1, 1)
void mgu_scan(const float* __restrict__ Uf, const float* __restrict__ Us,
              float* __restrict__ out) {
    extern __shared__ char smem[];
    ulonglong2* sWf = (ulonglong2*)smem;                  // [SW_J][256]
    ulonglong2* sWs = (ulonglong2*)(smem + SW_BYTES);
    char* vh  = smem + SH_OFF;                            // skewed h vector
    char* vfh = smem + SFH_OFF;                           // skewed f*h vector
    char* bFH = smem + BAR_OFF;                           // mbarrier (8B)
    char* bH  = smem + BAR_OFF + 16;                      // mbarrier (8B)

    const int t  = threadIdx.x;
    const int uL = t >> 1;
    const int kh = t & 1;
    const uint32_t rank = ctarank();
    const uint32_t peer = rank ^ 1u;
    const int ug = (int)rank * 128 + uL;      // this thread's unit
    const int b  = blockIdx.x >> 1;           // batch row
    const int Lb = (int)rank * 128 + kh * 64; // local-k base (own CTA produces)
    const int Rb = (int)peer * 128 + kh * 64; // remote-k base (peer produces)

    // ---- RF preload: local pairs 0..7 (k = Lb..Lb+15), remote pairs 0..31 ----
    ull rFl[RFLP], rSl[RFLP], rFr[RFRP], rSr[RFRP];
#pragma unroll
    for (int p = 0; p < RFLP; p++) {
        int k = Lb + 2 * p;
        rFl[p] = pack2(Uf[(size_t)k * UNITS + ug], Uf[(size_t)(k + 1) * UNITS + ug]);
        rSl[p] = pack2(Us[(size_t)k * UNITS + ug], Us[(size_t)(k + 1) * UNITS + ug]);
    }
#pragma unroll
    for (int p = 0; p < RFRP; p++) {
        int k = Rb + 2 * p;
        rFr[p] = pack2(Uf[(size_t)k * UNITS + ug], Uf[(size_t)(k + 1) * UNITS + ug]);
        rSr[p] = pack2(Us[(size_t)k * UNITS + ug], Us[(size_t)(k + 1) * UNITS + ug]);
    }
    // ---- smem preload: slot j -> local k = Lb + 16 + 4j ----
#pragma unroll
    for (int j = 0; j < SW_J; j++) {
        int kk = Lb + 16 + 4 * j;
        sWf[j * 256 + t] = make_ulonglong2(
            pack2(Uf[(size_t)kk       * UNITS + ug], Uf[(size_t)(kk + 1) * UNITS + ug]),
            pack2(Uf[(size_t)(kk + 2) * UNITS + ug], Uf[(size_t)(kk + 3) * UNITS + ug]));
        sWs[j * 256 + t] = make_ulonglong2(
            pack2(Us[(size_t)kk       * UNITS + ug], Us[(size_t)(kk + 1) * UNITS + ug]),
            pack2(Us[(size_t)(kk + 2) * UNITS + ug], Us[(size_t)(kk + 3) * UNITS + ug]));
    }
    // zero both vectors (incl. skew pads); init mbarriers (128 remote arrivals)
    for (int i = t; i < 2 * VEC_BYTES / 4; i += 256)
        ((float*)(smem + SH_OFF))[i] = 0.0f;
    if (t == 0) { mbar_init(bFH, 128); mbar_init(bH, 128); }
    __syncthreads();
    asm volatile("barrier.cluster.arrive.aligned;" ::: "memory");
    asm volatile("barrier.cluster.wait.aligned;"   ::: "memory");

    // Skewed addressing: addr(f) = f*4 + (f>>6)*16
    const int addrL = Lb * 4 + (Lb >> 6) * 16;
    const int addrR = Rb * 4 + (Rb >> 6) * 16;
    const ulonglong2* vhL  = (const ulonglong2*)(vh  + addrL);  // 16 slots
    const ulonglong2* vhR  = (const ulonglong2*)(vh  + addrR);
    const ulonglong2* vfhL = (const ulonglong2*)(vfh + addrL);
    const ulonglong2* vfhR = (const ulonglong2*)(vfh + addrR);
    const int aU = ug * 4 + (ug >> 6) * 16;
    float* myh  = (float*)(vh  + aU);
    float* myfh = (float*)(vfh + aU);

    uint32_t ra_fh = 0, ra_h = 0, ra_bFH = 0, ra_bH = 0;
    if (kh == 0) {
        ra_fh  = mapa_addr(myfh, peer);
        ra_h   = mapa_addr(myh,  peer);
        ra_bFH = mapa_addr(bFH,  peer);
        ra_bH  = mapa_addr(bH,   peer);
    }

    float h_reg = 0.0f;
    size_t xo = ((size_t)b * SEQ) * UNITS + ug;
    float xf_c = __ldcg(&g_xf[xo]);
    float xs_c = __ldcg(&g_xs[xo]);

    for (int step = 0; step < SEQ; step++) {
        // prefetch next step's x (full-step latency cover; padded arrays)
        float xf_n = __ldcg(&g_xf[xo + UNITS]);
        float xs_n = __ldcg(&g_xs[xo + UNITS]);

        // ======== phase 1: h @ U_f ========
        ull a0 = 0, a1 = 0, a2 = 0, a3 = 0;
#pragma unroll
        for (int j = 0; j < 4; j++) {               // local RF (8 pairs)
            ulonglong2 hv = vhL[j];
            fma2(a0, hv.x, rFl[2 * j]);
            fma2(a1, hv.y, rFl[2 * j + 1]);
        }
#pragma unroll
        for (int j = 0; j < SW_J; j++) {            // local smem (24 pairs)
            ulonglong2 hv = vhL[4 + j];
            ulonglong2 wv = sWf[j * 256 + t];
            fma2(a2, hv.x, wv.x);
            fma2(a3, hv.y, wv.y);
        }
        if (step) mbar_wait(bH, (step + 1) & 1);    // remote h(step-1) ready
#pragma unroll
        for (int j = 0; j < 16; j++) {              // remote RF (32 pairs)
            ulonglong2 hv = vhR[j];
            fma2(a0, hv.x, rFr[2 * j]);
            fma2(a1, hv.y, rFr[2 * j + 1]);
        }
        add2(a0, a1); add2(a2, a3); add2(a0, a2);
        float2 rr = unpack2(a0);
        float p = rr.x + rr.y;
        p += __shfl_xor_sync(0xffffffffu, p, 1);
        float f  = 1.0f / (1.0f + __expf(-(xf_c + p)));
        float fh = f * h_reg;
        if (kh == 0) {
            st_rlx_remote(ra_fh, fh);               // peer mirror
            mbar_arrive_remote(ra_bFH);             // signal peer (pre-barrier!)
            *myfh = fh;                             // local mirror
        }
        __syncthreads();                            // local ordering only

        // ======== phase 2: (f*h) @ U_s ========
        a0 = 0; a1 = 0; a2 = 0; a3 = 0;
#pragma unroll
        for (int j = 0; j < 4; j++) {               // local RF
            ulonglong2 hv = vfhL[j];
            fma2(a0, hv.x, rSl[2 * j]);
            fma2(a1, hv.y, rSl[2 * j + 1]);
        }
#pragma unroll
        for (int j = 0; j < SW_J; j++) {            // local smem
            ulonglong2 hv = vfhL[4 + j];
            ulonglong2 wv = sWs[j * 256 + t];
            fma2(a2, hv.x, wv.x);
            fma2(a3, hv.y, wv.y);
        }
        mbar_wait(bFH, step & 1);                   // remote fh ready
#pragma unroll
        for (int j = 0; j < 16; j++) {              // remote RF
            ulonglong2 hv = vfhR[j];
            fma2(a0, hv.x, rSr[2 * j]);
            fma2(a1, hv.y, rSr[2 * j + 1]);
        }
        add2(a0, a1); add2(a2, a3); add2(a0, a2);
        float2 qq = unpack2(a0);
        float q = qq.x + qq.y;
        q += __shfl_xor_sync(0xffffffffu, q, 1);

        float s  = xs_c + q;
        float ax = fabsf(s);
        float e  = __expf(-2.0f * ax);
        float th = copysignf((1.0f - e) / (1.0f + e), s);      // safe tanh

        float hn = h_reg + f * (th - h_reg);                   // (1-f)h + f*th
        if (kh == 0) {
            out[xo] = hn;
            st_rlx_remote(ra_h, hn);                // peer mirror
            mbar_arrive_remote(ra_bH);              // signal peer
            *myh = hn;                              // local mirror
        }
        h_reg = hn;
        xf_c = xf_n;
        xs_c = xs_n;
        xo += UNITS;
        __syncthreads();                            // local ordering only
    }

    // Don't exit while the peer may still write into our smem.
    asm volatile("barrier.cluster.arrive.aligned;" ::: "memory");
    asm volatile("barrier.cluster.wait.aligned;"   ::: "memory");
}

// ---------------------------------------------------------------------------
// Entry point
// ---------------------------------------------------------------------------
extern "C" void kernel_launch(void* const* d_in, const int* in_sizes, int n_in,
                              void* d_out, int out_size) {
    const float* X  = (const float*)d_in[0];
    const float* Wf = (const float*)d_in[1];
    const float* Uf = (const float*)d_in[2];
    const float* bf = (const float*)d_in[3];
    const float* Ws = (const float*)d_in[4];
    const float* Us = (const float*)d_in[5];
    const float* bs = (const float*)d_in[6];
    float* out = (float*)d_out;
    (void)in_sizes; (void)n_in; (void)out_size;

    cudaFuncSetAttribute(mgu_scan,
                         cudaFuncAttributeMaxDynamicSharedMemorySize, SMEM_SCAN);

    gemm_in<<<dim3(M_TOTAL / BM, 4), 256>>>(X, Wf, bf, Ws, bs);
    mgu_scan<<<2 * BATCH, 256, SMEM_SCAN>>>(Uf, Us, out);
}

// round 16
// speedup vs baseline: 1.2647x; 1.2647x over previous
#include <cuda_runtime.h>
#include <cstdint>
#include <cstddef>

// ---------------------------------------------------------------------------
// Problem dims (fixed)
// ---------------------------------------------------------------------------
#define BATCH 64
#define SEQ   2048
#define IND   256
#define UNITS 256
#define M_TOTAL (BATCH * SEQ)          // 131072

typedef unsigned long long ull;

// ---------------------------------------------------------------------------
// Device-global scratch (padded by UNITS for the x prefetch of the last step)
// ---------------------------------------------------------------------------
__device__ float g_xf[(size_t)M_TOTAL * UNITS + UNITS];
__device__ float g_xs[(size_t)M_TOTAL * UNITS + UNITS];

// ---------------------------------------------------------------------------
// Packed f32x2 helpers
// ---------------------------------------------------------------------------
__device__ __forceinline__ void fma2(ull& d, ull a, ull b) {
    asm("fma.rn.f32x2 %0, %1, %2, %0;" : "+l"(d) : "l"(a), "l"(b));
}
__device__ __forceinline__ void add2(ull& d, ull a) {
    asm("add.rn.f32x2 %0, %0, %1;" : "+l"(d) : "l"(a));
}
__device__ __forceinline__ ull pack2(float x, float y) {
    ull r;
    asm("mov.b64 %0, {%1, %2};" : "=l"(r)
        : "r"(__float_as_uint(x)), "r"(__float_as_uint(y)));
    return r;
}
__device__ __forceinline__ float2 unpack2(ull v) {
    unsigned lo, hi;
    asm("mov.b64 {%0, %1}, %2;" : "=r"(lo), "=r"(hi) : "l"(v));
    return make_float2(__uint_as_float(lo), __uint_as_float(hi));
}

// ---------------------------------------------------------------------------
// Phase 1: xf = X @ W_f + b_f ; xs = X @ W_s + b_s
// 2-stage register-staged double buffer: prefetch tile k0+BK LDGs during
// tile k0's FMAs; ONE __syncthreads per tile. Dynamic smem (48.5KB > 48KB
// static cap), 2 CTAs/SM. FMA order identical to the R14 gemm.
// ---------------------------------------------------------------------------
#define BM 128
#define BN 128
#define BK 16
#define GA_STRIDE (BM + 2)                     // ull stride per k-row
#define GA_BYTES  (BK * GA_STRIDE * 8)         // 16640 per buffer
#define GB_BYTES  (BK * BN * 4)                // 8192 per buffer
#define SMEM_GEMM (2 * (GA_BYTES + GB_BYTES))  // 49664

__global__ __launch_bounds__(256, 2)
void gemm_in(const float* __restrict__ X,
             const float* __restrict__ Wf, const float* __restrict__ bf,
             const float* __restrict__ Ws, const float* __restrict__ bs) {
    extern __shared__ char gsm[];
    // sA[buf][k][m] (ull, pre-duplicated), sB[buf][k][n]
    ull*   sA0 = (ull*)gsm;
    ull*   sA1 = (ull*)(gsm + GA_BYTES);
    float* sB0 = (float*)(gsm + 2 * GA_BYTES);
    float* sB1 = (float*)(gsm + 2 * GA_BYTES + GB_BYTES);

    const int tid = threadIdx.x;
    const int which = blockIdx.y;
    const float* W    = (which < 2) ? Wf : Ws;
    const float* bias = (which < 2) ? bf : bs;
    float*       out  = (which < 2) ? g_xf : g_xs;
    const int    n0   = (which & 1) * BN;
    const size_t m0   = (size_t)blockIdx.x * BM;

    const int tx = tid & 15;
    const int ty = tid >> 4;

    // per-thread load coordinates (2 slots each for A and B)
    int rowA[2], kqA[2], krB[2], nqB[2];
#pragma unroll
    for (int it = 0; it < 2; it++) {
        int s = tid + it * 256;
        rowA[it] = s >> 2;
        kqA[it]  = (s & 3) * 4;
        krB[it]  = s >> 5;
        nqB[it]  = (s & 31) * 4;
    }

    ull acc[8][4];
#pragma unroll
    for (int i = 0; i < 8; i++)
#pragma unroll
        for (int j = 0; j < 4; j++) acc[i][j] = 0ull;

    // prefetch tile k0 = 0 into registers
    float4 avr[2], bvr[2];
#pragma unroll
    for (int it = 0; it < 2; it++) {
        avr[it] = *(const float4*)&X[(m0 + rowA[it]) * IND + kqA[it]];
        bvr[it] = *(const float4*)&W[(size_t)krB[it] * UNITS + n0 + nqB[it]];
    }

    int buf = 0;
    for (int k0 = 0; k0 < IND; k0 += BK) {
        ull*   sA = buf ? sA1 : sA0;
        float* sB = buf ? sB1 : sB0;

        // store staged tile (A pre-duplicated)
#pragma unroll
        for (int it = 0; it < 2; it++) {
            ull* a = &sA[kqA[it] * GA_STRIDE + rowA[it]];
            a[0 * GA_STRIDE] = pack2(avr[it].x, avr[it].x);
            a[1 * GA_STRIDE] = pack2(avr[it].y, avr[it].y);
            a[2 * GA_STRIDE] = pack2(avr[it].z, avr[it].z);
            a[3 * GA_STRIDE] = pack2(avr[it].w, avr[it].w);
            *(float4*)&sB[krB[it] * BN + nqB[it]] = bvr[it];
        }
        __syncthreads();

        // prefetch next tile while computing this one
        if (k0 + BK < IND) {
#pragma unroll
            for (int it = 0; it < 2; it++) {
                avr[it] = *(const float4*)
                    &X[(m0 + rowA[it]) * IND + (k0 + BK) + kqA[it]];
                bvr[it] = *(const float4*)
                    &W[(size_t)(k0 + BK + krB[it]) * UNITS + n0 + nqB[it]];
            }
        }

#pragma unroll
        for (int k = 0; k < BK; k++) {
            ull a[8];
#pragma unroll
            for (int i = 0; i < 8; i++) a[i] = sA[k * GA_STRIDE + ty * 8 + i];
            const ull* b2 = (const ull*)&sB[k * BN + tx * 8];
            ull b[4];
#pragma unroll
            for (int j = 0; j < 4; j++) b[j] = b2[j];
#pragma unroll
            for (int i = 0; i < 8; i++)
#pragma unroll
                for (int j = 0; j < 4; j++) fma2(acc[i][j], a[i], b[j]);
        }
        buf ^= 1;
        // NOTE: no second sync. A warp's reads of this buffer precede its
        // arrival at the NEXT iteration's sync; writes to this buffer happen
        // two iterations later, after that sync.
    }

    float bv[8];
#pragma unroll
    for (int j = 0; j < 8; j++) bv[j] = bias[n0 + tx * 8 + j];
#pragma unroll
    for (int i = 0; i < 8; i++) {
        size_t row = m0 + ty * 8 + i;
        float2 r0 = unpack2(acc[i][0]);
        float2 r1 = unpack2(acc[i][1]);
        float2 r2 = unpack2(acc[i][2]);
        float2 r3 = unpack2(acc[i][3]);
        float4 o0 = make_float4(r0.x + bv[0], r0.y + bv[1],
                                r1.x + bv[2], r1.y + bv[3]);
        float4 o1 = make_float4(r2.x + bv[4], r2.y + bv[5],
                                r3.x + bv[6], r3.y + bv[7]);
        *(float4*)&out[row * UNITS + n0 + tx * 8]     = o0;
        *(float4*)&out[row * UNITS + n0 + tx * 8 + 4] = o1;
    }
}

// ---------------------------------------------------------------------------
// Phase 2: cluster-2 scan (R14 version, verbatim — best known).
// 128 CTAs. Thread = (unit uL = t>>1, kh = t&1); lane pair combines via
// shfl.bfly(1). Thread's 128-k = 64 LOCAL (no flag needed) + 64 REMOTE
// (flag-gated). Order: local RF (8 pairs) -> local smem (24 pairs) -> spin ->
// remote RF (32 pairs). Post-flag tail is pure register FMAs. Vectors skewed
// 16B per 64 floats for conflict-free dual-broadcast LDS.
// ---------------------------------------------------------------------------
#define RFLP 8                                // local RF pairs per matrix
#define RFRP 32                               // remote RF pairs per matrix
#define SW_J 12                               // local smem slots (24 pairs)
#define SW_BYTES (SW_J * 256 * 16)            // 49152 per matrix
#define VEC_BYTES 1088                        // 256 floats + 4x16B skew
#define SH_OFF   (2 * SW_BYTES)               // 98304
#define SFH_OFF  (SH_OFF + VEC_BYTES)
#define FLG_OFF  (SFH_OFF + VEC_BYTES)
#define SMEM_SCAN (FLG_OFF + 64)              // 100608 bytes

__device__ __forceinline__ uint32_t ctarank() {
    uint32_t r;
    asm("mov.u32 %0, %%cluster_ctarank;" : "=r"(r));
    return r;
}
__device__ __forceinline__ uint32_t mapa_addr(const void* laddr, uint32_t peer) {
    uint32_t la = (uint32_t)__cvta_generic_to_shared(laddr);
    uint32_t ra;
    asm("mapa.shared::cluster.u32 %0, %1, %2;" : "=r"(ra) : "r"(la), "r"(peer));
    return ra;
}
__device__ __forceinline__ void st_rlx_remote(uint32_t ra, float v) {
    asm volatile("st.relaxed.cluster.shared::cluster.b32 [%0], %1;"
                 :: "r"(ra), "r"(__float_as_uint(v)) : "memory");
}
__device__ __forceinline__ void st_rel_remote(uint32_t ra, uint32_t v) {
    asm volatile("st.release.cluster.shared::cluster.b32 [%0], %1;"
                 :: "r"(ra), "r"(v) : "memory");
}
__device__ __forceinline__ uint32_t ld_acq_local(const uint32_t* p) {
    uint32_t la = (uint32_t)__cvta_generic_to_shared(p);
    uint32_t v;
    asm volatile("ld.acquire.cluster.shared::cta.b32 %0, [%1];"
                 : "=r"(v) : "r"(la) : "memory");
    return v;
}
__device__ __forceinline__ void spin_ge(const uint32_t* flag, uint32_t want) {
    while (ld_acq_local(flag) < want) {}
}

__global__ __launch_bounds__(256, 1) __cluster_dims__(2, 1, 1)
void mgu_scan(const float* __restrict__ Uf, const float* __restrict__ Us,
              float* __restrict__ out) {
    extern __shared__ char smem[];
    ulonglong2* sWf = (ulonglong2*)smem;                  // [SW_J][256]
    ulonglong2* sWs = (ulonglong2*)(smem + SW_BYTES);
    char* vh  = smem + SH_OFF;                            // skewed h vector
    char* vfh = smem + SFH_OFF;                           // skewed f*h vector
    uint32_t* flg = (uint32_t*)(smem + FLG_OFF);          // [0]=H, [8]=FH

    const int t  = threadIdx.x;
    const int uL = t >> 1;
    const int kh = t & 1;
    const uint32_t rank = ctarank();
    const uint32_t peer = rank ^ 1u;
    const int ug = (int)rank * 128 + uL;      // this thread's unit
    const int b  = blockIdx.x >> 1;           // batch row
    const int Lb = (int)rank * 128 + kh * 64; // local-k base (own CTA produces)
    const int Rb = (int)peer * 128 + kh * 64; // remote-k base (peer produces)

    // ---- RF preload: local pairs 0..7 (k = Lb..Lb+15), remote pairs 0..31 ----
    ull rFl[RFLP], rSl[RFLP], rFr[RFRP], rSr[RFRP];
#pragma unroll
    for (int p = 0; p < RFLP; p++) {
        int k = Lb + 2 * p;
        rFl[p] = pack2(Uf[(size_t)k * UNITS + ug], Uf[(size_t)(k + 1) * UNITS + ug]);
        rSl[p] = pack2(Us[(size_t)k * UNITS + ug], Us[(size_t)(k + 1) * UNITS + ug]);
    }
#pragma unroll
    for (int p = 0; p < RFRP; p++) {
        int k = Rb + 2 * p;
        rFr[p] = pack2(Uf[(size_t)k * UNITS + ug], Uf[(size_t)(k + 1) * UNITS + ug]);
        rSr[p] = pack2(Us[(size_t)k * UNITS + ug], Us[(size_t)(k + 1) * UNITS + ug]);
    }
    // ---- smem preload: slot j -> local k = Lb + 16 + 4j ----
#pragma unroll
    for (int j = 0; j < SW_J; j++) {
        int kk = Lb + 16 + 4 * j;
        sWf[j * 256 + t] = make_ulonglong2(
            pack2(Uf[(size_t)kk       * UNITS + ug], Uf[(size_t)(kk + 1) * UNITS + ug]),
            pack2(Uf[(size_t)(kk + 2) * UNITS + ug], Uf[(size_t)(kk + 3) * UNITS + ug]));
        sWs[j * 256 + t] = make_ulonglong2(
            pack2(Us[(size_t)kk       * UNITS + ug], Us[(size_t)(kk + 1) * UNITS + ug]),
            pack2(Us[(size_t)(kk + 2) * UNITS + ug], Us[(size_t)(kk + 3) * UNITS + ug]));
    }
    // zero both vectors (incl. skew pads) + flags
    for (int i = t; i < 2 * VEC_BYTES / 4; i += 256)
        ((float*)(smem + SH_OFF))[i] = 0.0f;
    if (t == 0) { flg[0] = 0u; flg[8] = 0u; }
    __syncthreads();
    asm volatile("barrier.cluster.arrive.aligned;" ::: "memory");
    asm volatile("barrier.cluster.wait.aligned;"   ::: "memory");

    // Skewed addressing: addr(f) = f*4 + (f>>6)*16
    const int addrL = Lb * 4 + (Lb >> 6) * 16;
    const int addrR = Rb * 4 + (Rb >> 6) * 16;
    const ulonglong2* vhL  = (const ulonglong2*)(vh  + addrL);  // 16 slots
    const ulonglong2* vhR  = (const ulonglong2*)(vh  + addrR);
    const ulonglong2* vfhL = (const ulonglong2*)(vfh + addrL);
    const ulonglong2* vfhR = (const ulonglong2*)(vfh + addrR);
    const int aU = ug * 4 + (ug >> 6) * 16;
    float* myh  = (float*)(vh  + aU);
    float* myfh = (float*)(vfh + aU);

    uint32_t ra_fh = 0, ra_h = 0, ra_flag_fh = 0, ra_flag_h = 0;
    if (kh == 0) {
        ra_fh = mapa_addr(myfh, peer);
        ra_h  = mapa_addr(myh,  peer);
    }
    if (t == 0) {
        ra_flag_h  = mapa_addr(&flg[0], peer);
        ra_flag_fh = mapa_addr(&flg[8], peer);
    }

    float h_reg = 0.0f;
    size_t xo = ((size_t)b * SEQ) * UNITS + ug;
    float xf_c = __ldcg(&g_xf[xo]);
    float xs_c = __ldcg(&g_xs[xo]);

    for (int step = 0; step < SEQ; step++) {
        // prefetch next step's x (full-step latency cover; padded arrays)
        float xf_n = __ldcg(&g_xf[xo + UNITS]);
        float xs_n = __ldcg(&g_xs[xo + UNITS]);

        // ======== phase 1: h @ U_f ========
        ull a0 = 0, a1 = 0, a2 = 0, a3 = 0;
#pragma unroll
        for (int j = 0; j < 4; j++) {               // local RF (8 pairs)
            ulonglong2 hv = vhL[j];
            fma2(a0, hv.x, rFl[2 * j]);
            fma2(a1, hv.y, rFl[2 * j + 1]);
        }
#pragma unroll
        for (int j = 0; j < SW_J; j++) {            // local smem (24 pairs)
            ulonglong2 hv = vhL[4 + j];
            ulonglong2 wv = sWf[j * 256 + t];
            fma2(a2, hv.x, wv.x);
            fma2(a3, hv.y, wv.y);
        }
        spin_ge(&flg[0], (uint32_t)step);           // remote h ready?
#pragma unroll
        for (int j = 0; j < 16; j++) {              // remote RF (32 pairs)
            ulonglong2 hv = vhR[j];
            fma2(a0, hv.x, rFr[2 * j]);
            fma2(a1, hv.y, rFr[2 * j + 1]);
        }
        add2(a0, a1); add2(a2, a3); add2(a0, a2);
        float2 rr = unpack2(a0);
        float p = rr.x + rr.y;
        p += __shfl_xor_sync(0xffffffffu, p, 1);
        float f  = 1.0f / (1.0f + __expf(-(xf_c + p)));
        float fh = f * h_reg;
        if (kh == 0) { st_rlx_remote(ra_fh, fh); *myfh = fh; }
        __syncthreads();                                       // S_a
        if (t == 0) st_rel_remote(ra_flag_fh, (uint32_t)(step + 1));

        // ======== phase 2: (f*h) @ U_s ========
        a0 = 0; a1 = 0; a2 = 0; a3 = 0;
#pragma unroll
        for (int j = 0; j < 4; j++) {               // local RF
            ulonglong2 hv = vfhL[j];
            fma2(a0, hv.x, rSl[2 * j]);
            fma2(a1, hv.y, rSl[2 * j + 1]);
        }
#pragma unroll
        for (int j = 0; j < SW_J; j++) {            // local smem
            ulonglong2 hv = vfhL[4 + j];
            ulonglong2 wv = sWs[j * 256 + t];
            fma2(a2, hv.x, wv.x);
            fma2(a3, hv.y, wv.y);
        }
        spin_ge(&flg[8], (uint32_t)(step + 1));     // remote fh ready?
#pragma unroll
        for (int j = 0; j < 16; j++) {              // remote RF
            ulonglong2 hv = vfhR[j];
            fma2(a0, hv.x, rSr[2 * j]);
            fma2(a1, hv.y, rSr[2 * j + 1]);
        }
        add2(a0, a1); add2(a2, a3); add2(a0, a2);
        float2 qq = unpack2(a0);
        float q = qq.x + qq.y;
        q += __shfl_xor_sync(0xffffffffu, q, 1);

        float s  = xs_c + q;
        float ax = fabsf(s);
        float e  = __expf(-2.0f * ax);
        float th = copysignf((1.0f - e) / (1.0f + e), s);      // safe tanh

        float hn = h_reg + f * (th - h_reg);                   // (1-f)h + f*th
        if (kh == 0) {
            out[xo] = hn;
            st_rlx_remote(ra_h, hn);
            *myh = hn;
        }
        h_reg = hn;
        xf_c = xf_n;
        xs_c = xs_n;
        xo += UNITS;
        __syncthreads();                                       // S_b
        if (t == 0) st_rel_remote(ra_flag_h, (uint32_t)(step + 1));
    }

    // Don't exit while the peer may still write into our smem.
    asm volatile("barrier.cluster.arrive.aligned;" ::: "memory");
    asm volatile("barrier.cluster.wait.aligned;"   ::: "memory");
}

// ---------------------------------------------------------------------------
// Entry point
// ---------------------------------------------------------------------------
extern "C" void kernel_launch(void* const* d_in, const int* in_sizes, int n_in,
                              void* d_out, int out_size) {
    const float* X  = (const float*)d_in[0];
    const float* Wf = (const float*)d_in[1];
    const float* Uf = (const float*)d_in[2];
    const float* bf = (const float*)d_in[3];
    const float* Ws = (const float*)d_in[4];
    const float* Us = (const float*)d_in[5];
    const float* bs = (const float*)d_in[6];
    float* out = (float*)d_out;
    (void)in_sizes; (void)n_in; (void)out_size;

    cudaFuncSetAttribute(gemm_in,
                         cudaFuncAttributeMaxDynamicSharedMemorySize, SMEM_GEMM);
    cudaFuncSetAttribute(mgu_scan,
                         cudaFuncAttributeMaxDynamicSharedMemorySize, SMEM_SCAN);

    gemm_in<<<dim3(M_TOTAL / BM, 4), 256, SMEM_GEMM>>>(X, Wf, bf, Ws, bs);
    mgu_scan<<<2 * BATCH, 256, SMEM_SCAN>>>(Uf, Us, out);
}